// round 2
// baseline (speedup 1.0000x reference)
#include <cuda_runtime.h>

// Inputs (metadata order; int64 in the reference are narrowed to int32 by the harness):
//   d_in[0]: y      float32 (T, B, 7)
//   d_in[1]: t      int32   (T, B, 3)   values in {0,1}
//   d_in[2]: y_len  int32   (B,)
// Output: float32 scalar

#define CHUNK 8

__global__ void zero_out_kernel(float* out) {
    if (threadIdx.x == 0) out[0] = 0.0f;
}

__global__ __launch_bounds__(512)
void ce_loss_kernel(const float* __restrict__ y,
                    const int* __restrict__ tgt,
                    const int* __restrict__ y_len,
                    float* __restrict__ out,
                    int T, int B)
{
    const int b  = threadIdx.x;          // b in [0, B)
    const int t0 = blockIdx.x * CHUNK;

    const int len = y_len[b];
    float acc = 0.0f;

    // valid timesteps for this sample within this chunk
    int tend = t0 + CHUNK;
    if (tend > T) tend = T;
    int lend = len < tend ? len : tend;

    #pragma unroll 2
    for (int t = t0; t < lend; ++t) {
        const long long idx = (long long)t * B + b;
        const float* yr = y + idx * 7;
        // 7 contiguous floats; warp-coalesced across lanes (stride 28B)
        float l0 = yr[0], l1 = yr[1], l2 = yr[2];
        float l3 = yr[3], l4 = yr[4];
        float l5 = yr[5], l6 = yr[6];

        const int* tr = tgt + idx * 3;
        int c0 = tr[0], c1 = tr[1], c2 = tr[2];

        // group 0: 3-class CE
        float m0 = fmaxf(l0, fmaxf(l1, l2));
        float s0 = __expf(l0 - m0) + __expf(l1 - m0) + __expf(l2 - m0);
        float sel0 = (c0 == 0) ? l0 : ((c0 == 1) ? l1 : l2);
        acc += m0 + __logf(s0) - sel0;

        // group 1: 2-class CE (cols 3,4)
        float m1 = fmaxf(l3, l4);
        float s1 = __expf(l3 - m1) + __expf(l4 - m1);
        float sel1 = (c1 == 0) ? l3 : l4;
        acc += m1 + __logf(s1) - sel1;

        // group 2: 2-class CE (cols 5,6)
        float m2 = fmaxf(l5, l6);
        float s2 = __expf(l5 - m2) + __expf(l6 - m2);
        float sel2 = (c2 == 0) ? l5 : l6;
        acc += m2 + __logf(s2) - sel2;
    }

    // per-sample normalization folded in per-thread (linear across chunks)
    float contrib = (len > 0) ? acc / (float)len : 0.0f;

    // block tree reduction over 512 threads
    __shared__ float sdata[512];
    sdata[b] = contrib;
    __syncthreads();
    #pragma unroll
    for (int s = 256; s > 32; s >>= 1) {
        if (b < s) sdata[b] += sdata[b + s];
        __syncthreads();
    }
    if (b < 32) {
        float v = sdata[b] + sdata[b + 32];
        #pragma unroll
        for (int off = 16; off > 0; off >>= 1)
            v += __shfl_down_sync(0xFFFFFFFFu, v, off);
        if (b == 0 && v != 0.0f)
            atomicAdd(out, v / (float)B);
    }
}

extern "C" void kernel_launch(void* const* d_in, const int* in_sizes, int n_in,
                              void* d_out, int out_size)
{
    const float* y    = (const float*)d_in[0];
    const int*   tgt  = (const int*)d_in[1];
    const int*   ylen = (const int*)d_in[2];
    float* out = (float*)d_out;

    const int B = in_sizes[2];                 // 512
    const int T = in_sizes[0] / (B * 7);       // 4096

    zero_out_kernel<<<1, 32>>>(out);

    const int nblocks = (T + CHUNK - 1) / CHUNK;   // 512
    ce_loss_kernel<<<nblocks, B>>>(y, tgt, ylen, out, T, B);
}

// round 3
// speedup vs baseline: 1.3582x; 1.3582x over previous
#include <cuda_runtime.h>

// Inputs (metadata order; reference int64 narrowed to int32 by harness):
//   d_in[0]: y      float32 (T, B, 7)
//   d_in[1]: t      int32   (T, B, 3)
//   d_in[2]: y_len  int32   (B,)
// Output: float32 scalar
//
// Strategy: one thread handles 4 consecutive b at one timestep t.
// 4 rows of y = 112 contiguous bytes (16B aligned) -> 7x float4 loads.
// 4 rows of t = 48 contiguous bytes -> 3x int4 loads.

#define TPB 256

__global__ void zero_out_kernel(float* out) {
    if (threadIdx.x == 0) out[0] = 0.0f;
}

__device__ __forceinline__ float ce_row(float l0, float l1, float l2,
                                        float l3, float l4,
                                        float l5, float l6,
                                        int c0, int c1, int c2)
{
    // group 0: 3-class
    float m0 = fmaxf(l0, fmaxf(l1, l2));
    float s0 = __expf(l0 - m0) + __expf(l1 - m0) + __expf(l2 - m0);
    float sel0 = (c0 == 0) ? l0 : ((c0 == 1) ? l1 : l2);
    float r = m0 + __logf(s0) - sel0;
    // group 1: 2-class
    float m1 = fmaxf(l3, l4);
    float s1 = __expf(l3 - m1) + __expf(l4 - m1);
    r += m1 + __logf(s1) - ((c1 == 0) ? l3 : l4);
    // group 2: 2-class
    float m2 = fmaxf(l5, l6);
    float s2 = __expf(l5 - m2) + __expf(l6 - m2);
    r += m2 + __logf(s2) - ((c2 == 0) ? l5 : l6);
    return r;
}

__global__ __launch_bounds__(TPB)
void ce_loss_kernel(const float4* __restrict__ y4,
                    const int4* __restrict__ t4,
                    const int4* __restrict__ len4,
                    float* __restrict__ out,
                    int T, int B)
{
    const int BG  = B >> 2;                          // b-groups of 4
    const int tid = blockIdx.x * TPB + threadIdx.x;
    const int t   = tid / BG;
    const int bg  = tid - t * BG;

    float contrib = 0.0f;

    const int4 L = len4[bg];                         // lengths for b0..b3 (L1/L2 resident)
    const int maxlen = max(max(L.x, L.y), max(L.z, L.w));

    if (t < T && t < maxlen) {
        const long long e  = (long long)t * B + (bg << 2);  // element index of b0
        const long long q  = e >> 2;                        // e/4 (e is mult of 4)
        const float4* yb = y4 + q * 7;
        const int4*   tb = t4 + q * 3;

        // 10 independent wide loads — high MLP
        float4 v0 = yb[0], v1 = yb[1], v2 = yb[2], v3 = yb[3];
        float4 v4 = yb[4], v5 = yb[5], v6 = yb[6];
        int4 i0 = tb[0], i1 = tb[1], i2 = tb[2];

        // b0: v0.xyzw v1.xyz | i0.xyz
        if (t < L.x)
            contrib += __fdividef(
                ce_row(v0.x, v0.y, v0.z, v0.w, v1.x, v1.y, v1.z,
                       i0.x, i0.y, i0.z), (float)L.x);
        // b1: v1.w v2.xyzw v3.xy | i0.w i1.xy
        if (t < L.y)
            contrib += __fdividef(
                ce_row(v1.w, v2.x, v2.y, v2.z, v2.w, v3.x, v3.y,
                       i0.w, i1.x, i1.y), (float)L.y);
        // b2: v3.zw v4.xyzw v5.x | i1.zw i2.x
        if (t < L.z)
            contrib += __fdividef(
                ce_row(v3.z, v3.w, v4.x, v4.y, v4.z, v4.w, v5.x,
                       i1.z, i1.w, i2.x), (float)L.z);
        // b3: v5.yzw v6.xyzw | i2.yzw
        if (t < L.w)
            contrib += __fdividef(
                ce_row(v5.y, v5.z, v5.w, v6.x, v6.y, v6.z, v6.w,
                       i2.y, i2.z, i2.w), (float)L.w);
    }

    // warp reduce
    #pragma unroll
    for (int off = 16; off > 0; off >>= 1)
        contrib += __shfl_down_sync(0xFFFFFFFFu, contrib, off);

    __shared__ float wsum[TPB / 32];
    const int lane = threadIdx.x & 31;
    const int wid  = threadIdx.x >> 5;
    if (lane == 0) wsum[wid] = contrib;
    __syncthreads();

    if (threadIdx.x < TPB / 32) {
        float v = wsum[threadIdx.x];
        #pragma unroll
        for (int off = (TPB / 64); off > 0; off >>= 1)
            v += __shfl_down_sync(0xFFu, v, off);
        if (threadIdx.x == 0 && v != 0.0f)
            atomicAdd(out, v * (1.0f / (float)B));
    }
}

extern "C" void kernel_launch(void* const* d_in, const int* in_sizes, int n_in,
                              void* d_out, int out_size)
{
    const float4* y4   = (const float4*)d_in[0];
    const int4*   t4   = (const int4*)d_in[1];
    const int4*   len4 = (const int4*)d_in[2];
    float* out = (float*)d_out;

    const int B = in_sizes[2];                 // 512
    const int T = in_sizes[0] / (B * 7);       // 4096
    const int BG = B >> 2;                     // 128

    zero_out_kernel<<<1, 32>>>(out);

    const long long total = (long long)T * BG; // 524288
    const int nblocks = (int)((total + TPB - 1) / TPB);
    ce_loss_kernel<<<nblocks, TPB>>>(y4, t4, len4, out, T, B);
}